// round 16
// baseline (speedup 1.0000x reference)
#include <cuda_runtime.h>
#include <cstdint>

// ---------------------------------------------------------------------------
// DAS beamformer — replicates XLA's compiled f32 chain:
//   m  = rn(rn(mask*1000) + 128)                      (separate mul/add, no FMA)
//   vx = rn(rn(rn(x - idx) + 1) * DX);  sx = rn(vx*vx)
//   d2 = rn(sx + sy);  dis = sqrt.rn(d2)
//   t  = trunc( rn( rn(dis * rn(1/1500)) * 12500000.0f ) )
// (XLA algsimp rewrites divide-by-constant -> multiply-by-reciprocal.)
//   out[b, iy, ix] = (image - min_b) / (max_b - min_b)
// Inner loop: packed f32x2 chain (2 gathers per sequence). Per-component the
// ops are IEEE RN, identical to scalar. sqrt via RSQ + 1 Newton matches
// sqrt.rn except ~2^-20 probability 1-ulp cases (<0.1 expected flips total).
// ---------------------------------------------------------------------------

static constexpr float DXc   = 0.001f;
static constexpr float DYc   = 0.001f;
static constexpr float DTF   = (float)(1.0 / 12500000.0);
static constexpr float RCPVS = (float)(1.0 / 1500.0);          // rn(1/1500)
static constexpr float RCPDT = (float)(1.0 / (double)DTF);     // == 12500000.0f

// scratch: eight sensor-eighth planes of un-normalized sums per batch.
// plane (e*8 + b), pixel p = ix*256 + iy.
__device__ float g_scratch[64 * 65536];
__device__ float g_comb[8 * 65536];      // combined per-batch image (minmax writes)
__device__ float g_pmn[64], g_pmx[64];   // per-(batch, chunk) partial min/max

// exact chain (used for window bounds only)
__device__ __forceinline__ int t_chain(float d2) {
    float dis = __fsqrt_rn(d2);
    float q1  = __fmul_rn(dis, RCPVS);
    float q2  = __fmul_rn(q1, RCPDT);
    return __float2int_rz(q2);
}

// Packed 2-wide t computation: d2 = sx + sy; dis = RSQ+Newton sqrt;
// t = trunc(dis * RCPVS * RCPDT). All packed ops are per-component IEEE RN.
// Caller guarantees d2 > 0 (sxt table is clamped to >= 1e-30).
__device__ __forceinline__ void t2_fast(uint64_t sx2, uint64_t sy2,
                                        uint64_t half2, uint64_t sgn2,
                                        uint64_t rcpvs2, uint64_t rcpdt2,
                                        int &ta, int &tb)
{
    asm("{\n\t"
        ".reg .f32 lo, hi, rl, rh, qa, qb;\n\t"
        ".reg .b64 d2, r2, y2, h2, e2, ds, p1, p2, yn;\n\t"
        "add.rn.f32x2 d2, %2, %3;\n\t"
        "mov.b64 {lo, hi}, d2;\n\t"
        "rsqrt.approx.f32 rl, lo;\n\t"
        "rsqrt.approx.f32 rh, hi;\n\t"
        "mov.b64 r2, {rl, rh};\n\t"
        "mul.rn.f32x2 y2, d2, r2;\n\t"
        "mul.rn.f32x2 h2, r2, %4;\n\t"
        "xor.b64 yn, y2, %5;\n\t"
        "fma.rn.f32x2 e2, yn, y2, d2;\n\t"
        "fma.rn.f32x2 ds, e2, h2, y2;\n\t"
        "mul.rn.f32x2 p1, ds, %6;\n\t"
        "mul.rn.f32x2 p2, p1, %7;\n\t"
        "mov.b64 {qa, qb}, p2;\n\t"
        "cvt.rzi.s32.f32 %0, qa;\n\t"
        "cvt.rzi.s32.f32 %1, qb;\n\t"
        "}"
        : "=r"(ta), "=r"(tb)
        : "l"(sx2), "l"(sy2), "l"(half2), "l"(sgn2),
          "l"(rcpvs2), "l"(rcpdt2));
}

// ---------------------------------------------------------------------------
// Kernel 1: per-CTA 32x32 pixel tile x 16-sensor eighth, 256 threads.
// Quad-unrolled sensor loop: one barrier / one cp.async group per 4 sensors,
// 8 window buffers (staging quad q+1 while computing quad q).
// Window range for a 32x32 tile <= 31*sqrt(2)*DX/VS/DT (365.4) + 16 pad + 3
// align < 448 floats, so WCAP4=112 provably covers every gather (the pad also
// absorbs the <=1-ulp t difference between fast and exact chains).
// ---------------------------------------------------------------------------
#define WCAP4 112                  // window capacity: 112 float4 = 448 floats
#define NSTG  8                    // pipeline depth (buffers) = 2 quads
#define NSEN  16                   // sensors per CTA (eighth of 128)

__global__ void __launch_bounds__(256, 8)
das_main(const float* __restrict__ sd, const float* __restrict__ mask)
{
    __shared__ float win[NSTG][WCAP4 * 4];
    __shared__ __align__(16) float sxt[NSEN * 32];    // sx = max(rn(vx*vx), 1e-30)
    __shared__ __align__(16) uint64_t syt2[NSEN * 32];// {sy, sy} packed pairs
    __shared__ float smx[NSEN], smy[NSEN];
    __shared__ int   swb[NSEN], swn[NSEN];

    const int zb  = blockIdx.z;
    const int b   = zb >> 3;             // batch
    const int egt = zb & 7;              // sensor eighth 0..7
    const int s_base = egt << 4;         // sensor base: 0,16,...,112
    const int ix0 = blockIdx.x * 32;     // 0-based pixel tile origin
    const int iy0 = blockIdx.y * 32;
    const int tid = threadIdx.x;
    const int iy_off = tid & 31;         // this thread's iy within the tile
    const int ixg    = tid >> 5;         // ix group 0..7 (4 ix each)

    // packed constants for the f32x2 chain
    const uint32_t rvu = __float_as_uint(RCPVS);
    const uint32_t rdu = __float_as_uint(RCPDT);
    const uint64_t RCPVS2 = ((uint64_t)rvu << 32) | rvu;
    const uint64_t RCPDT2 = ((uint64_t)rdu << 32) | rdu;
    const uint64_t HALF2  = 0x3F0000003F000000ULL;   // {0.5f, 0.5f}
    const uint64_t SGN2   = 0x8000000080000000ULL;   // sign bits

    // ---- phase A: per-sensor coordinates + staging window bounds -----------
    if (tid < NSEN) {
        int sg = s_base + tid;
        float mxv = mask[((b * 128 + sg) << 1) + 0];
        float myv = mask[((b * 128 + sg) << 1) + 1];
        // separate mul then add (no FMA) — matches HLO mul + add
        float xm = __fadd_rn(__fmul_rn(mxv, 1000.0f), 128.0f);
        float ym = __fadd_rn(__fmul_rn(myv, 1000.0f), 128.0f);
        smx[tid] = xm;
        smy[tid] = ym;

        // corner (1-based) idx values of this tile
        float xl = (float)(ix0 + 1), xh = (float)(ix0 + 32);
        float yl = (float)(iy0 + 1), yh = (float)(iy0 + 32);

        // max distance over tile: at a corner (monotone exact chain per corner)
        float ax0 = __fadd_rn(__fsub_rn(xm, xl), 1.0f);
        float ax1 = __fadd_rn(__fsub_rn(xm, xh), 1.0f);
        float ay0 = __fadd_rn(__fsub_rn(ym, yl), 1.0f);
        float ay1 = __fadd_rn(__fsub_rn(ym, yh), 1.0f);
        float vx0 = __fmul_rn(ax0, DXc), vx1 = __fmul_rn(ax1, DXc);
        float vy0 = __fmul_rn(ay0, DYc), vy1 = __fmul_rn(ay1, DYc);
        float sx0 = __fmul_rn(vx0, vx0), sx1 = __fmul_rn(vx1, vx1);
        float sy0 = __fmul_rn(vy0, vy0), sy1 = __fmul_rn(vy1, vy1);
        float d2max = __fadd_rn(fmaxf(sx0, sx1), fmaxf(sy0, sy1));

        // min distance over tile: continuous clamp (lower bound), pad covers slop
        float ux = xm + 1.0f, uy = ym + 1.0f;   // sensor position in idx units
        float exd = fmaxf(fmaxf(xl - ux, ux - xh), 0.0f);
        float eyd = fmaxf(fmaxf(yl - uy, uy - yh), 0.0f);
        float vmx = exd * DXc, vmy = eyd * DYc;
        float d2min = vmx * vmx + vmy * vmy;

        int tmin = t_chain(d2min) - 8; if (tmin < 0) tmin = 0;
        int tmax = t_chain(d2max) + 8; if (tmax > 16383) tmax = 16383;

        int wb  = tmin & ~3;                       // 16B-aligned base
        int n4  = ((tmax - wb + 1) + 3) >> 2;      // float4 count
        int mx4 = (16384 - wb) >> 2;
        if (n4 > mx4)   n4 = mx4;
        if (n4 > WCAP4) n4 = WCAP4;                // provably never binds (<=97)
        swb[tid] = wb;
        swn[tid] = n4;
    }
    __syncthreads();

    // ---- phase B: precompute sx / sy term tables (exact chains) ------------
    #pragma unroll
    for (int i = tid; i < NSEN * 32; i += 256) {
        int s = i >> 5, l = i & 31;
        float xm  = smx[s], ym = smy[s];
        float ixf = (float)(ix0 + l + 1);
        float iyf = (float)(iy0 + l + 1);
        float ax  = __fadd_rn(__fsub_rn(xm, ixf), 1.0f);
        float vx  = __fmul_rn(ax, DXc);
        // clamp: changes d2 only when sx is 0/denormal, where t=0 either way.
        sxt[i] = fmaxf(__fmul_rn(vx, vx), 1e-30f);
        float ay  = __fadd_rn(__fsub_rn(ym, iyf), 1.0f);
        float vy  = __fmul_rn(ay, DYc);
        float sy  = __fmul_rn(vy, vy);
        uint32_t su = __float_as_uint(sy);
        syt2[i] = ((uint64_t)su << 32) | su;       // pre-packed {sy, sy}
    }
    __syncthreads();

    const float* row_base = sd + (size_t)b * 128 * 16384 + (size_t)s_base * 16384;
    const uint32_t sxt_base  = (uint32_t)__cvta_generic_to_shared(sxt);
    const uint32_t syt2_base = (uint32_t)__cvta_generic_to_shared(syt2);

    auto stage = [&](int s) {   // caller guarantees tid < 128 (warps 0..3)
        const int bi = s & (NSTG - 1);
        int wb = swb[s];
        if (tid < swn[s]) {
            const float* g = row_base + (size_t)s * 16384 + wb + tid * 4;
            uint32_t sa = (uint32_t)__cvta_generic_to_shared(&win[bi][tid * 4]);
            asm volatile("cp.async.cg.shared.global [%0], [%1], 16;\n"
                         :: "r"(sa), "l"(g) : "memory");
        }
    };

    // prologue: stage quad 0 (sensors 0..3) as one group
    if (tid < 128) { stage(0); stage(1); stage(2); stage(3); }
    asm volatile("cp.async.commit_group;\n" ::: "memory");

    float acc0 = 0.0f, acc1 = 0.0f, acc2 = 0.0f, acc3 = 0.0f;

    for (int s = 0; s < NSEN; s += 4) {
        // one pending group at entry (quad s) — committed one full quad ago
        asm volatile("cp.async.wait_group 0;\n" ::: "memory");
        __syncthreads();   // quad s ready; everyone done reading quad s-1 buffers

        if (tid < 128) {
            if (s + 4 < NSEN) { stage(s + 4); stage(s + 5); stage(s + 6); stage(s + 7); }
        }
        asm volatile("cp.async.commit_group;\n" ::: "memory");  // keep count invariant

        #pragma unroll
        for (int j = 0; j < 4; ++j) {
            const int ss = s + j;
            const float* w = &win[ss & (NSTG - 1)][0] - swb[ss]; // pre-offset base
            uint64_t sy2;
            uint32_t ya = syt2_base + (ss << 8) + (iy_off << 3);
            asm("ld.shared.b64 %0, [%1];" : "=l"(sy2) : "r"(ya));
            uint32_t sa = sxt_base + (ss << 7) + (ixg << 4);     // byte addr of sx pair
            uint64_t sx01, sx23;
            asm("ld.shared.b64 %0, [%1];" : "=l"(sx01) : "r"(sa));
            asm("ld.shared.b64 %0, [%1];" : "=l"(sx23) : "r"(sa + 8));

            int t0, t1, t2, t3;
            t2_fast(sx01, sy2, HALF2, SGN2, RCPVS2, RCPDT2, t0, t1);
            t2_fast(sx23, sy2, HALF2, SGN2, RCPVS2, RCPDT2, t2, t3);
            acc0 = __fadd_rn(acc0, w[t0]);
            acc1 = __fadd_rn(acc1, w[t1]);
            acc2 = __fadd_rn(acc2, w[t2]);
            acc3 = __fadd_rn(acc3, w[t3]);
        }
    }

    // write un-normalized partial sums: plane (eighth*8 + b)
    float* osc = g_scratch + (egt * 8 + b) * 65536
               + (ix0 + ixg * 4) * 256 + iy0 + iy_off;
    osc[0]   = acc0;
    osc[256] = acc1;
    osc[512] = acc2;
    osc[768] = acc3;
}

// ---------------------------------------------------------------------------
// Kernel 2: per-(batch, chunk) combine 8 planes + partial min/max, coalesced.
// Writes the combined image to g_comb (read by das_norm_t — bitwise identical).
// grid = 64 (8 batches x 8 chunks of 8192), 256 threads.
// ---------------------------------------------------------------------------
__global__ void __launch_bounds__(256)
das_minmax()
{
    __shared__ float rmn[256], rmx[256];
    const int b     = blockIdx.x >> 3;
    const int chunk = blockIdx.x & 7;
    const int tid   = threadIdx.x;
    const int off   = b * 65536 + chunk * 8192;
    const float* p0 = g_scratch + off;
    float* cb = g_comb + off;

    float mn =  3.402823466e38f;
    float mx = -3.402823466e38f;
    #pragma unroll 2
    for (int i = tid; i < 8192; i += 256) {
        float v01 = __fadd_rn(p0[i],               p0[i +  8 * 65536]);
        float v23 = __fadd_rn(p0[i + 16 * 65536],  p0[i + 24 * 65536]);
        float v45 = __fadd_rn(p0[i + 32 * 65536],  p0[i + 40 * 65536]);
        float v67 = __fadd_rn(p0[i + 48 * 65536],  p0[i + 56 * 65536]);
        float v = __fadd_rn(__fadd_rn(v01, v23), __fadd_rn(v45, v67));
        cb[i] = v;
        mn = fminf(mn, v);
        mx = fmaxf(mx, v);
    }
    rmn[tid] = mn; rmx[tid] = mx;
    __syncthreads();
    for (int o = 128; o > 0; o >>= 1) {
        if (tid < o) {
            rmn[tid] = fminf(rmn[tid], rmn[tid + o]);
            rmx[tid] = fmaxf(rmx[tid], rmx[tid + o]);
        }
        __syncthreads();
    }
    if (tid == 0) { g_pmn[blockIdx.x] = rmn[0]; g_pmx[blockIdx.x] = rmx[0]; }
}

// ---------------------------------------------------------------------------
// Kernel 3: normalize + transpose via 32x32 smem tiles, coalesced both ways.
// grid = (64, 8): 64 tiles per batch. block 256 = 32x8.
// ---------------------------------------------------------------------------
__global__ void __launch_bounds__(256)
das_norm_t(float* __restrict__ out)
{
    __shared__ float tile[32][33];
    const int b  = blockIdx.y;
    const int tx = blockIdx.x & 7;   // ix tile
    const int ty = blockIdx.x >> 3;  // iy tile
    const int lx = threadIdx.x & 31;
    const int lr = threadIdx.x >> 5; // 0..7

    // reduce the 8 per-batch partials (redundant per CTA, trivial)
    float mn = g_pmn[b * 8 + 0], mx = g_pmx[b * 8 + 0];
    #pragma unroll
    for (int c = 1; c < 8; ++c) {
        mn = fminf(mn, g_pmn[b * 8 + c]);
        mx = fmaxf(mx, g_pmx[b * 8 + c]);
    }
    float den = __fsub_rn(mx, mn);

    const float* img = g_comb + b * 65536;
    // load: rows are ix (tx*32 + r), cols iy (ty*32 + lx) — coalesced
    #pragma unroll
    for (int r = lr; r < 32; r += 8) {
        tile[r][lx] = img[(tx * 32 + r) * 256 + ty * 32 + lx];
    }
    __syncthreads();

    float* ob = out + b * 65536;
    // store: out[b, iy, ix] — rows iy (ty*32 + r), cols ix (tx*32 + lx) — coalesced
    #pragma unroll
    for (int r = lr; r < 32; r += 8) {
        float v = tile[lx][r];
        ob[(ty * 32 + r) * 256 + tx * 32 + lx] = __fdiv_rn(__fsub_rn(v, mn), den);
    }
}

// ---------------------------------------------------------------------------
extern "C" void kernel_launch(void* const* d_in, const int* in_sizes, int n_in,
                              void* d_out, int out_size)
{
    const float* sd   = (const float*)d_in[0];   // (8,128,16384) f32
    const float* mask = (const float*)d_in[1];   // (8,128,2) f32
    float* out = (float*)d_out;                  // (8,256,256) f32

    // z = batch*8 + sensor-eighth: 4096 CTAs at 8 CTAs/SM
    dim3 grid(8, 8, 64);
    das_main<<<grid, 256>>>(sd, mask);
    das_minmax<<<64, 256>>>();
    das_norm_t<<<dim3(64, 8), 256>>>(out);
}

// round 17
// speedup vs baseline: 1.1029x; 1.1029x over previous
#include <cuda_runtime.h>
#include <cstdint>

// ---------------------------------------------------------------------------
// DAS beamformer — replicates XLA's compiled f32 chain:
//   m  = rn(rn(mask*1000) + 128)                      (separate mul/add, no FMA)
//   vx = rn(rn(rn(x - idx) + 1) * DX);  sx = rn(vx*vx)
//   d2 = rn(sx + sy);  dis = sqrt.rn(d2)
//   t  = trunc( rn( rn(dis * rn(1/1500)) * 12500000.0f ) )
// (XLA algsimp rewrites divide-by-constant -> multiply-by-reciprocal.)
//   out[b, iy, ix] = (image - min_b) / (max_b - min_b)
// Inner loop: packed f32x2 chain (2 gathers per sequence). Per-component the
// ops are IEEE RN, identical to scalar. sqrt via RSQ + 1 Newton matches
// sqrt.rn except ~2^-20 probability 1-ulp cases (<0.1 expected flips total).
// ---------------------------------------------------------------------------

static constexpr float DXc   = 0.001f;
static constexpr float DYc   = 0.001f;
static constexpr float DTF   = (float)(1.0 / 12500000.0);
static constexpr float RCPVS = (float)(1.0 / 1500.0);          // rn(1/1500)
static constexpr float RCPDT = (float)(1.0 / (double)DTF);     // == 12500000.0f

// scratch: eight sensor-eighth planes of un-normalized sums per batch.
// plane (e*8 + b), pixel p = ix*256 + iy.
__device__ float g_scratch[64 * 65536];
__device__ float g_comb[8 * 65536];        // combined per-batch image (minmax writes)
__device__ float g_pmn[512], g_pmx[512];   // per-(batch, chunk) partial min/max

// exact chain (used for window bounds only)
__device__ __forceinline__ int t_chain(float d2) {
    float dis = __fsqrt_rn(d2);
    float q1  = __fmul_rn(dis, RCPVS);
    float q2  = __fmul_rn(q1, RCPDT);
    return __float2int_rz(q2);
}

// Packed 2-wide t computation: d2 = sx + sy; dis = RSQ+Newton sqrt;
// t = trunc(dis * RCPVS * RCPDT). All packed ops are per-component IEEE RN.
// Caller guarantees d2 > 0 (sxt table is clamped to >= 1e-30).
__device__ __forceinline__ void t2_fast(uint64_t sx2, uint64_t sy2,
                                        uint64_t half2, uint64_t sgn2,
                                        uint64_t rcpvs2, uint64_t rcpdt2,
                                        int &ta, int &tb)
{
    asm("{\n\t"
        ".reg .f32 lo, hi, rl, rh, qa, qb;\n\t"
        ".reg .b64 d2, r2, y2, h2, e2, ds, p1, p2, yn;\n\t"
        "add.rn.f32x2 d2, %2, %3;\n\t"
        "mov.b64 {lo, hi}, d2;\n\t"
        "rsqrt.approx.f32 rl, lo;\n\t"
        "rsqrt.approx.f32 rh, hi;\n\t"
        "mov.b64 r2, {rl, rh};\n\t"
        "mul.rn.f32x2 y2, d2, r2;\n\t"
        "mul.rn.f32x2 h2, r2, %4;\n\t"
        "xor.b64 yn, y2, %5;\n\t"
        "fma.rn.f32x2 e2, yn, y2, d2;\n\t"
        "fma.rn.f32x2 ds, e2, h2, y2;\n\t"
        "mul.rn.f32x2 p1, ds, %6;\n\t"
        "mul.rn.f32x2 p2, p1, %7;\n\t"
        "mov.b64 {qa, qb}, p2;\n\t"
        "cvt.rzi.s32.f32 %0, qa;\n\t"
        "cvt.rzi.s32.f32 %1, qb;\n\t"
        "}"
        : "=r"(ta), "=r"(tb)
        : "l"(sx2), "l"(sy2), "l"(half2), "l"(sgn2),
          "l"(rcpvs2), "l"(rcpdt2));
}

// ---------------------------------------------------------------------------
// Kernel 1: per-CTA 32x32 pixel tile x 16-sensor eighth, 256 threads.
// Quad-unrolled sensor loop: one barrier / one cp.async group per 4 sensors,
// 8 window buffers (staging quad q+1 while computing quad q).
// Window range for a 32x32 tile <= 31*sqrt(2)*DX/VS/DT (365.4) + 16 pad + 3
// align < 448 floats, so WCAP4=112 provably covers every gather (the pad also
// absorbs the <=1-ulp t difference between fast and exact chains).
// ---------------------------------------------------------------------------
#define WCAP4 112                  // window capacity: 112 float4 = 448 floats
#define NSTG  8                    // pipeline depth (buffers) = 2 quads
#define NSEN  16                   // sensors per CTA (eighth of 128)

__global__ void __launch_bounds__(256, 8)
das_main(const float* __restrict__ sd, const float* __restrict__ mask)
{
    __shared__ float win[NSTG][WCAP4 * 4];
    __shared__ __align__(16) float sxt[NSEN * 32];    // sx = max(rn(vx*vx), 1e-30)
    __shared__ __align__(16) uint64_t syt2[NSEN * 32];// {sy, sy} packed pairs
    __shared__ float smx[NSEN], smy[NSEN];
    __shared__ int   swb[NSEN], swn[NSEN];

    const int zb  = blockIdx.z;
    const int b   = zb >> 3;             // batch
    const int egt = zb & 7;              // sensor eighth 0..7
    const int s_base = egt << 4;         // sensor base: 0,16,...,112
    const int ix0 = blockIdx.x * 32;     // 0-based pixel tile origin
    const int iy0 = blockIdx.y * 32;
    const int tid = threadIdx.x;
    const int iy_off = tid & 31;         // this thread's iy within the tile
    const int ixg    = tid >> 5;         // ix group 0..7 (4 ix each)

    // packed constants for the f32x2 chain
    const uint32_t rvu = __float_as_uint(RCPVS);
    const uint32_t rdu = __float_as_uint(RCPDT);
    const uint64_t RCPVS2 = ((uint64_t)rvu << 32) | rvu;
    const uint64_t RCPDT2 = ((uint64_t)rdu << 32) | rdu;
    const uint64_t HALF2  = 0x3F0000003F000000ULL;   // {0.5f, 0.5f}
    const uint64_t SGN2   = 0x8000000080000000ULL;   // sign bits

    // ---- phase A: per-sensor coordinates + staging window bounds -----------
    if (tid < NSEN) {
        int sg = s_base + tid;
        float mxv = mask[((b * 128 + sg) << 1) + 0];
        float myv = mask[((b * 128 + sg) << 1) + 1];
        // separate mul then add (no FMA) — matches HLO mul + add
        float xm = __fadd_rn(__fmul_rn(mxv, 1000.0f), 128.0f);
        float ym = __fadd_rn(__fmul_rn(myv, 1000.0f), 128.0f);
        smx[tid] = xm;
        smy[tid] = ym;

        // corner (1-based) idx values of this tile
        float xl = (float)(ix0 + 1), xh = (float)(ix0 + 32);
        float yl = (float)(iy0 + 1), yh = (float)(iy0 + 32);

        // max distance over tile: at a corner (monotone exact chain per corner)
        float ax0 = __fadd_rn(__fsub_rn(xm, xl), 1.0f);
        float ax1 = __fadd_rn(__fsub_rn(xm, xh), 1.0f);
        float ay0 = __fadd_rn(__fsub_rn(ym, yl), 1.0f);
        float ay1 = __fadd_rn(__fsub_rn(ym, yh), 1.0f);
        float vx0 = __fmul_rn(ax0, DXc), vx1 = __fmul_rn(ax1, DXc);
        float vy0 = __fmul_rn(ay0, DYc), vy1 = __fmul_rn(ay1, DYc);
        float sx0 = __fmul_rn(vx0, vx0), sx1 = __fmul_rn(vx1, vx1);
        float sy0 = __fmul_rn(vy0, vy0), sy1 = __fmul_rn(vy1, vy1);
        float d2max = __fadd_rn(fmaxf(sx0, sx1), fmaxf(sy0, sy1));

        // min distance over tile: continuous clamp (lower bound), pad covers slop
        float ux = xm + 1.0f, uy = ym + 1.0f;   // sensor position in idx units
        float exd = fmaxf(fmaxf(xl - ux, ux - xh), 0.0f);
        float eyd = fmaxf(fmaxf(yl - uy, uy - yh), 0.0f);
        float vmx = exd * DXc, vmy = eyd * DYc;
        float d2min = vmx * vmx + vmy * vmy;

        int tmin = t_chain(d2min) - 8; if (tmin < 0) tmin = 0;
        int tmax = t_chain(d2max) + 8; if (tmax > 16383) tmax = 16383;

        int wb  = tmin & ~3;                       // 16B-aligned base
        int n4  = ((tmax - wb + 1) + 3) >> 2;      // float4 count
        int mx4 = (16384 - wb) >> 2;
        if (n4 > mx4)   n4 = mx4;
        if (n4 > WCAP4) n4 = WCAP4;                // provably never binds (<=97)
        swb[tid] = wb;
        swn[tid] = n4;
    }
    __syncthreads();

    // ---- phase B: precompute sx / sy term tables (exact chains) ------------
    #pragma unroll
    for (int i = tid; i < NSEN * 32; i += 256) {
        int s = i >> 5, l = i & 31;
        float xm  = smx[s], ym = smy[s];
        float ixf = (float)(ix0 + l + 1);
        float iyf = (float)(iy0 + l + 1);
        float ax  = __fadd_rn(__fsub_rn(xm, ixf), 1.0f);
        float vx  = __fmul_rn(ax, DXc);
        // clamp: changes d2 only when sx is 0/denormal, where t=0 either way.
        sxt[i] = fmaxf(__fmul_rn(vx, vx), 1e-30f);
        float ay  = __fadd_rn(__fsub_rn(ym, iyf), 1.0f);
        float vy  = __fmul_rn(ay, DYc);
        float sy  = __fmul_rn(vy, vy);
        uint32_t su = __float_as_uint(sy);
        syt2[i] = ((uint64_t)su << 32) | su;       // pre-packed {sy, sy}
    }
    __syncthreads();

    const float* row_base = sd + (size_t)b * 128 * 16384 + (size_t)s_base * 16384;
    const uint32_t sxt_base  = (uint32_t)__cvta_generic_to_shared(sxt);
    const uint32_t syt2_base = (uint32_t)__cvta_generic_to_shared(syt2);

    auto stage = [&](int s) {   // caller guarantees tid < 128 (warps 0..3)
        const int bi = s & (NSTG - 1);
        int wb = swb[s];
        if (tid < swn[s]) {
            const float* g = row_base + (size_t)s * 16384 + wb + tid * 4;
            uint32_t sa = (uint32_t)__cvta_generic_to_shared(&win[bi][tid * 4]);
            asm volatile("cp.async.cg.shared.global [%0], [%1], 16;\n"
                         :: "r"(sa), "l"(g) : "memory");
        }
    };

    // prologue: stage quad 0 (sensors 0..3) as one group
    if (tid < 128) { stage(0); stage(1); stage(2); stage(3); }
    asm volatile("cp.async.commit_group;\n" ::: "memory");

    float acc0 = 0.0f, acc1 = 0.0f, acc2 = 0.0f, acc3 = 0.0f;

    for (int s = 0; s < NSEN; s += 4) {
        // one pending group at entry (quad s) — committed one full quad ago
        asm volatile("cp.async.wait_group 0;\n" ::: "memory");
        __syncthreads();   // quad s ready; everyone done reading quad s-1 buffers

        if (tid < 128) {
            if (s + 4 < NSEN) { stage(s + 4); stage(s + 5); stage(s + 6); stage(s + 7); }
        }
        asm volatile("cp.async.commit_group;\n" ::: "memory");  // keep count invariant

        #pragma unroll
        for (int j = 0; j < 4; ++j) {
            const int ss = s + j;
            const float* w = &win[ss & (NSTG - 1)][0] - swb[ss]; // pre-offset base
            uint64_t sy2;
            uint32_t ya = syt2_base + (ss << 8) + (iy_off << 3);
            asm("ld.shared.b64 %0, [%1];" : "=l"(sy2) : "r"(ya));
            uint32_t sa = sxt_base + (ss << 7) + (ixg << 4);     // byte addr of sx pair
            uint64_t sx01, sx23;
            asm("ld.shared.b64 %0, [%1];" : "=l"(sx01) : "r"(sa));
            asm("ld.shared.b64 %0, [%1];" : "=l"(sx23) : "r"(sa + 8));

            int t0, t1, t2, t3;
            t2_fast(sx01, sy2, HALF2, SGN2, RCPVS2, RCPDT2, t0, t1);
            t2_fast(sx23, sy2, HALF2, SGN2, RCPVS2, RCPDT2, t2, t3);
            acc0 = __fadd_rn(acc0, w[t0]);
            acc1 = __fadd_rn(acc1, w[t1]);
            acc2 = __fadd_rn(acc2, w[t2]);
            acc3 = __fadd_rn(acc3, w[t3]);
        }
    }

    // write un-normalized partial sums: plane (eighth*8 + b)
    float* osc = g_scratch + (egt * 8 + b) * 65536
               + (ix0 + ixg * 4) * 256 + iy0 + iy_off;
    osc[0]   = acc0;
    osc[256] = acc1;
    osc[512] = acc2;
    osc[768] = acc3;
}

// ---------------------------------------------------------------------------
// Kernel 2: combine 8 planes + partial min/max, full-chip parallel.
// grid = 512 (8 batches x 64 chunks of 1024 pixels), 256 threads.
// Writes the combined image to g_comb (read by das_norm_t — bitwise identical).
// ---------------------------------------------------------------------------
__global__ void __launch_bounds__(256)
das_minmax()
{
    __shared__ float rmn[256], rmx[256];
    const int b     = blockIdx.x >> 6;       // batch
    const int chunk = blockIdx.x & 63;       // 64 chunks of 1024
    const int tid   = threadIdx.x;
    const int off   = b * 65536 + chunk * 1024;
    const float* p0 = g_scratch + off;
    float* cb = g_comb + off;

    float mn =  3.402823466e38f;
    float mx = -3.402823466e38f;
    #pragma unroll
    for (int i = tid; i < 1024; i += 256) {
        float v01 = __fadd_rn(p0[i],               p0[i +  8 * 65536]);
        float v23 = __fadd_rn(p0[i + 16 * 65536],  p0[i + 24 * 65536]);
        float v45 = __fadd_rn(p0[i + 32 * 65536],  p0[i + 40 * 65536]);
        float v67 = __fadd_rn(p0[i + 48 * 65536],  p0[i + 56 * 65536]);
        float v = __fadd_rn(__fadd_rn(v01, v23), __fadd_rn(v45, v67));
        cb[i] = v;
        mn = fminf(mn, v);
        mx = fmaxf(mx, v);
    }
    rmn[tid] = mn; rmx[tid] = mx;
    __syncthreads();
    for (int o = 128; o > 0; o >>= 1) {
        if (tid < o) {
            rmn[tid] = fminf(rmn[tid], rmn[tid + o]);
            rmx[tid] = fmaxf(rmx[tid], rmx[tid + o]);
        }
        __syncthreads();
    }
    if (tid == 0) { g_pmn[blockIdx.x] = rmn[0]; g_pmx[blockIdx.x] = rmx[0]; }
}

// ---------------------------------------------------------------------------
// Kernel 3: normalize + transpose via 32x32 smem tiles, coalesced both ways.
// grid = (64, 8): 64 tiles per batch. block 256 = 32x8.
// ---------------------------------------------------------------------------
__global__ void __launch_bounds__(256)
das_norm_t(float* __restrict__ out)
{
    __shared__ float tile[32][33];
    const int b  = blockIdx.y;
    const int tx = blockIdx.x & 7;   // ix tile
    const int ty = blockIdx.x >> 3;  // iy tile
    const int lx = threadIdx.x & 31;
    const int lr = threadIdx.x >> 5; // 0..7

    // reduce the 64 per-batch partials (uniform L2-hot loads, trivial)
    float mn = g_pmn[b * 64 + 0], mx = g_pmx[b * 64 + 0];
    #pragma unroll 8
    for (int c = 1; c < 64; ++c) {
        mn = fminf(mn, g_pmn[b * 64 + c]);
        mx = fmaxf(mx, g_pmx[b * 64 + c]);
    }
    float den = __fsub_rn(mx, mn);

    const float* img = g_comb + b * 65536;
    // load: rows are ix (tx*32 + r), cols iy (ty*32 + lx) — coalesced
    #pragma unroll
    for (int r = lr; r < 32; r += 8) {
        tile[r][lx] = img[(tx * 32 + r) * 256 + ty * 32 + lx];
    }
    __syncthreads();

    float* ob = out + b * 65536;
    // store: out[b, iy, ix] — rows iy (ty*32 + r), cols ix (tx*32 + lx) — coalesced
    #pragma unroll
    for (int r = lr; r < 32; r += 8) {
        float v = tile[lx][r];
        ob[(ty * 32 + r) * 256 + tx * 32 + lx] = __fdiv_rn(__fsub_rn(v, mn), den);
    }
}

// ---------------------------------------------------------------------------
extern "C" void kernel_launch(void* const* d_in, const int* in_sizes, int n_in,
                              void* d_out, int out_size)
{
    const float* sd   = (const float*)d_in[0];   // (8,128,16384) f32
    const float* mask = (const float*)d_in[1];   // (8,128,2) f32
    float* out = (float*)d_out;                  // (8,256,256) f32

    // z = batch*8 + sensor-eighth: 4096 CTAs at 8 CTAs/SM
    dim3 grid(8, 8, 64);
    das_main<<<grid, 256>>>(sd, mask);
    das_minmax<<<512, 256>>>();
    das_norm_t<<<dim3(64, 8), 256>>>(out);
}